// round 10
// baseline (speedup 1.0000x reference)
#include <cuda_runtime.h>
#include <math.h>
#include <stdint.h>

// Problem constants
#define BB   2
#define TT   4096
#define CC   768
#define HH   12
#define HD   64
#define MM   (BB*TT)        // 8192 rows
#define NQKV (3*CC)         // 2304

// Scratch (no cudaMalloc allowed)
__device__ float g_qkv[(size_t)MM * NQKV];
__device__ float g_y[(size_t)MM * CC];

// ----------------------------------------------------------------------------
// TF32 helpers
// ----------------------------------------------------------------------------
__device__ __forceinline__ float tf32r(float x) {
    uint32_t r;
    asm("cvt.rna.tf32.f32 %0, %1;" : "=r"(r) : "f"(x));
    return __uint_as_float(r);
}

__device__ __forceinline__ uint32_t tf32u(float x) {
    uint32_t r;
    asm("cvt.rna.tf32.f32 %0, %1;" : "=r"(r) : "f"(x));
    return r;
}

__device__ __forceinline__ void mma_tf32(float* d, const uint32_t* a,
                                         uint32_t b0, uint32_t b1) {
    asm volatile(
        "mma.sync.aligned.m16n8k8.row.col.f32.tf32.tf32.f32 "
        "{%0,%1,%2,%3}, {%4,%5,%6,%7}, {%8,%9}, {%0,%1,%2,%3};\n"
        : "+f"(d[0]), "+f"(d[1]), "+f"(d[2]), "+f"(d[3])
        : "r"(a[0]), "r"(a[1]), "r"(a[2]), "r"(a[3]), "r"(b0), "r"(b1));
}

__device__ __forceinline__ void cp_async16(void* smem_dst, const void* gmem_src) {
    uint32_t s = (uint32_t)__cvta_generic_to_shared(smem_dst);
    asm volatile("cp.async.cg.shared.global [%0], [%1], 16;" :: "r"(s), "l"(gmem_src));
}

// ----------------------------------------------------------------------------
// TF32 tensor-core GEMM (R7-measured: 248us QKV). Stride 136, conflict-free
// fragment loads. Block 128x128, BK=16, 8 warps (2m x 4n). UNCHANGED.
// ----------------------------------------------------------------------------
__global__ __launch_bounds__(256)
void gemm_tf32_bias(const float* __restrict__ A, const float* __restrict__ Bm,
                    const float* __restrict__ bias, float* __restrict__ Cm,
                    int M, int N, int K)
{
    __shared__ float As[16][136];
    __shared__ float Bs[16][136];

    const int tid  = threadIdx.x;
    const int lane = tid & 31, warp = tid >> 5;
    const int quad = lane >> 2, ql = lane & 3;
    const int wm = (warp & 1) * 64;
    const int wn = (warp >> 1) * 32;
    const int cm = blockIdx.y * 128, cn = blockIdx.x * 128;

    const int arow = tid >> 2, acol = (tid & 3) << 2;
    const int brow = tid >> 5, bcol = (tid & 31) << 2;

    const float* Ab = A + (size_t)cm * K;
    const float* Bb = Bm + cn;

    float acc[4][4][4];
#pragma unroll
    for (int mt = 0; mt < 4; ++mt)
#pragma unroll
        for (int nt = 0; nt < 4; ++nt)
#pragma unroll
            for (int f = 0; f < 4; ++f) acc[mt][nt][f] = 0.f;

    float4 pa0 = *(const float4*)(Ab + (size_t)arow * K + acol);
    float4 pa1 = *(const float4*)(Ab + (size_t)(arow + 64) * K + acol);
    float4 pb0 = *(const float4*)(Bb + (size_t)brow * N + bcol);
    float4 pb1 = *(const float4*)(Bb + (size_t)(brow + 8) * N + bcol);

    const int NK = K >> 4;
    for (int kt = 0; kt < NK; ++kt) {
        As[acol + 0][arow]      = tf32r(pa0.x);
        As[acol + 1][arow]      = tf32r(pa0.y);
        As[acol + 2][arow]      = tf32r(pa0.z);
        As[acol + 3][arow]      = tf32r(pa0.w);
        As[acol + 0][arow + 64] = tf32r(pa1.x);
        As[acol + 1][arow + 64] = tf32r(pa1.y);
        As[acol + 2][arow + 64] = tf32r(pa1.z);
        As[acol + 3][arow + 64] = tf32r(pa1.w);
        float4 tb;
        tb.x = tf32r(pb0.x); tb.y = tf32r(pb0.y);
        tb.z = tf32r(pb0.z); tb.w = tf32r(pb0.w);
        *(float4*)&Bs[brow][bcol] = tb;
        tb.x = tf32r(pb1.x); tb.y = tf32r(pb1.y);
        tb.z = tf32r(pb1.z); tb.w = tf32r(pb1.w);
        *(float4*)&Bs[brow + 8][bcol] = tb;
        __syncthreads();

        if (kt + 1 < NK) {
            const int k0 = (kt + 1) << 4;
            pa0 = *(const float4*)(Ab + (size_t)arow * K + k0 + acol);
            pa1 = *(const float4*)(Ab + (size_t)(arow + 64) * K + k0 + acol);
            pb0 = *(const float4*)(Bb + (size_t)(k0 + brow) * N + bcol);
            pb1 = *(const float4*)(Bb + (size_t)(k0 + brow + 8) * N + bcol);
        }

#pragma unroll
        for (int ks = 0; ks < 2; ++ks) {
            const int kk = ks * 8;
            uint32_t af[4][4];
#pragma unroll
            for (int mt = 0; mt < 4; ++mt) {
                const int mb = wm + mt * 16;
                af[mt][0] = __float_as_uint(As[kk + ql][mb + quad]);
                af[mt][1] = __float_as_uint(As[kk + ql][mb + quad + 8]);
                af[mt][2] = __float_as_uint(As[kk + ql + 4][mb + quad]);
                af[mt][3] = __float_as_uint(As[kk + ql + 4][mb + quad + 8]);
            }
#pragma unroll
            for (int nt = 0; nt < 4; ++nt) {
                const uint32_t b0 = __float_as_uint(Bs[kk + ql][wn + nt * 8 + quad]);
                const uint32_t b1 = __float_as_uint(Bs[kk + ql + 4][wn + nt * 8 + quad]);
#pragma unroll
                for (int mt = 0; mt < 4; ++mt)
                    mma_tf32(acc[mt][nt], af[mt], b0, b1);
            }
        }
        __syncthreads();
    }

#pragma unroll
    for (int mt = 0; mt < 4; ++mt) {
        const int r0 = cm + wm + mt * 16 + quad;
#pragma unroll
        for (int nt = 0; nt < 4; ++nt) {
            const int c = cn + wn + nt * 8 + ql * 2;
            const float bx = bias[c], by = bias[c + 1];
            float2 w;
            w.x = acc[mt][nt][0] + bx; w.y = acc[mt][nt][1] + by;
            *(float2*)(Cm + (size_t)r0 * N + c) = w;
            w.x = acc[mt][nt][2] + bx; w.y = acc[mt][nt][3] + by;
            *(float2*)(Cm + (size_t)(r0 + 8) * N + c) = w;
        }
    }
}

// ----------------------------------------------------------------------------
// Flash attention v3: warp m-tile 32, cp.async double-buffered K/V.
// K/V land in smem as raw f32; tf32 conversion happens in registers after
// each fragment LDS (bit-identical numerics to store-time conversion).
// Layouts: Qs [256][68], Ps [256][68], Ks [2][64][68], Vs [2][64][72].
// smem = (2*256*68 + 2*64*68 + 2*64*72) * 4 = 210944 B -> 1 CTA/SM.
// ----------------------------------------------------------------------------
#define FSK 68
#define FSV 72
#define FA_SMEM_BYTES ((2 * 256 * FSK + 2 * 64 * FSK + 2 * 64 * FSV) * sizeof(float))

__global__ __launch_bounds__(256, 1)
void flash_attn_tf32_kernel(const float* __restrict__ qkv, float* __restrict__ y)
{
    extern __shared__ float sm[];
    float* Qs  = sm;                        // [256][68]
    float* Ps  = Qs + 256 * FSK;            // [256][68]
    float* Ksb = Ps + 256 * FSK;            // [2][64][68]
    float* Vsb = Ksb + 2 * 64 * FSK;        // [2][64][72]

    const int tid  = threadIdx.x;
    const int warp = tid >> 5;
    const int lane = tid & 31;
    const int quad = lane >> 2;
    const int ql   = lane & 3;
    const int h  = blockIdx.y;
    const int b  = blockIdx.z;
    const int q0 = blockIdx.x * 256;
    const size_t rowBase = (size_t)b * TT;
    const int qOff = h * HD, kOff = CC + h * HD, vOff = 2 * CC + h * HD;

    const int rq = warp * 32 + quad;

    // cp.async per-thread mapping for K/V tiles: 4 float4 each
    const int lr = tid >> 2;                 // 0..63 rows, 4 threads/row
    const int lc = (tid & 3) << 4;           // 0,16,32,48 col base (x4 floats)

    // ---- issue tile 0 K/V prefetch ----
    {
        const size_t g = (rowBase + lr) * NQKV;
#pragma unroll
        for (int cc4 = 0; cc4 < 4; ++cc4) {
            const int c = lc + cc4 * 4;
            cp_async16(&Ksb[lr * FSK + c], qkv + g + kOff + c);
            cp_async16(&Vsb[lr * FSV + c], qkv + g + vOff + c);
        }
    }
    asm volatile("cp.async.commit_group;");

    // ---- load Q tile (256 x 64), converted ----
#pragma unroll
    for (int p = 0; p < 16; ++p) {
        const int f4 = tid + 256 * p;
        const int r = f4 >> 4, c = (f4 & 15) << 2;
        const float4 v = *(const float4*)(qkv + (rowBase + q0 + r) * NQKV + qOff + c);
        Qs[r * FSK + c + 0] = tf32r(v.x);
        Qs[r * FSK + c + 1] = tf32r(v.y);
        Qs[r * FSK + c + 2] = tf32r(v.z);
        Qs[r * FSK + c + 3] = tf32r(v.w);
    }
    __syncthreads();

    // ---- mt0 Q fragments in registers ----
    uint32_t qa0[8][4];
#pragma unroll
    for (int ks = 0; ks < 8; ++ks) {
        const int c = ks * 8 + ql;
        qa0[ks][0] = __float_as_uint(Qs[rq * FSK + c]);
        qa0[ks][1] = __float_as_uint(Qs[(rq + 8) * FSK + c]);
        qa0[ks][2] = __float_as_uint(Qs[rq * FSK + c + 4]);
        qa0[ks][3] = __float_as_uint(Qs[(rq + 8) * FSK + c + 4]);
    }

    float m[4], l[4];
#pragma unroll
    for (int i = 0; i < 4; ++i) { m[i] = -INFINITY; l[i] = 0.f; }
    int qrow[4];
    qrow[0] = q0 + rq;       qrow[1] = q0 + rq + 8;
    qrow[2] = q0 + rq + 16;  qrow[3] = q0 + rq + 24;
    const int wmax = q0 + warp * 32 + 31;

    float o[2][8][4];
#pragma unroll
    for (int mt = 0; mt < 2; ++mt)
#pragma unroll
        for (int t = 0; t < 8; ++t)
            o[mt][t][0] = o[mt][t][1] = o[mt][t][2] = o[mt][t][3] = 0.f;

    const float C2 = 0.18033688011112042f;   // log2(e) / sqrt(64)

    const int nkt = (q0 >> 6) + 4;
    for (int kt = 0; kt < nkt; ++kt) {
        const int k0 = kt << 6;
        float* Ks = Ksb + (kt & 1) * 64 * FSK;
        float* Vs = Vsb + (kt & 1) * 64 * FSV;

        // issue next tile into other buffer, then wait for current
        if (kt + 1 < nkt) {
            float* Kn = Ksb + ((kt + 1) & 1) * 64 * FSK;
            float* Vn = Vsb + ((kt + 1) & 1) * 64 * FSV;
            const size_t g = (rowBase + (kt + 1) * 64 + lr) * NQKV;
#pragma unroll
            for (int cc4 = 0; cc4 < 4; ++cc4) {
                const int c = lc + cc4 * 4;
                cp_async16(&Kn[lr * FSK + c], qkv + g + kOff + c);
                cp_async16(&Vn[lr * FSV + c], qkv + g + vOff + c);
            }
            asm volatile("cp.async.commit_group;");
            asm volatile("cp.async.wait_group 1;");
        } else {
            asm volatile("cp.async.wait_group 0;");
        }
        __syncthreads();

        if (k0 <= wmax) {   // compute only if tile not fully masked for this warp
            // ---- S = Q K^T ----
            float sacc[2][8][4];
#pragma unroll
            for (int mt = 0; mt < 2; ++mt)
#pragma unroll
                for (int t = 0; t < 8; ++t)
                    sacc[mt][t][0] = sacc[mt][t][1] = sacc[mt][t][2] = sacc[mt][t][3] = 0.f;
#pragma unroll
            for (int ks = 0; ks < 8; ++ks) {
                const int c = ks * 8 + ql;
                uint32_t qa1[4];
                qa1[0] = __float_as_uint(Qs[(rq + 16) * FSK + c]);
                qa1[1] = __float_as_uint(Qs[(rq + 24) * FSK + c]);
                qa1[2] = __float_as_uint(Qs[(rq + 16) * FSK + c + 4]);
                qa1[3] = __float_as_uint(Qs[(rq + 24) * FSK + c + 4]);
#pragma unroll
                for (int t = 0; t < 8; ++t) {
                    const uint32_t b0 = tf32u(Ks[(t * 8 + quad) * FSK + c]);
                    const uint32_t b1 = tf32u(Ks[(t * 8 + quad) * FSK + c + 4]);
                    mma_tf32(sacc[0][t], qa0[ks], b0, b1);
                    mma_tf32(sacc[1][t], qa1, b0, b1);
                }
            }

            // ---- scale + causal mask + row max ----
            float rm[4];
            rm[0] = rm[1] = rm[2] = rm[3] = -INFINITY;
#pragma unroll
            for (int mt = 0; mt < 2; ++mt)
#pragma unroll
                for (int t = 0; t < 8; ++t) {
                    const int gc = k0 + t * 8 + ql * 2;
                    float v0 = sacc[mt][t][0] * C2; if (gc     > qrow[2*mt])   v0 = -INFINITY;
                    float v1 = sacc[mt][t][1] * C2; if (gc + 1 > qrow[2*mt])   v1 = -INFINITY;
                    float v2 = sacc[mt][t][2] * C2; if (gc     > qrow[2*mt+1]) v2 = -INFINITY;
                    float v3 = sacc[mt][t][3] * C2; if (gc + 1 > qrow[2*mt+1]) v3 = -INFINITY;
                    sacc[mt][t][0] = v0; sacc[mt][t][1] = v1;
                    sacc[mt][t][2] = v2; sacc[mt][t][3] = v3;
                    rm[2*mt]   = fmaxf(rm[2*mt],   fmaxf(v0, v1));
                    rm[2*mt+1] = fmaxf(rm[2*mt+1], fmaxf(v2, v3));
                }
            float mn[4], al[4];
#pragma unroll
            for (int i = 0; i < 4; ++i) {
                rm[i] = fmaxf(rm[i], __shfl_xor_sync(0xffffffffu, rm[i], 1));
                rm[i] = fmaxf(rm[i], __shfl_xor_sync(0xffffffffu, rm[i], 2));
                mn[i] = fmaxf(m[i], rm[i]);
                al[i] = exp2f(m[i] - mn[i]);
            }

            // ---- exp, P write, O rescale ----
            float sum[4];
            sum[0] = sum[1] = sum[2] = sum[3] = 0.f;
#pragma unroll
            for (int mt = 0; mt < 2; ++mt) {
                const int r0 = rq + mt * 16;
#pragma unroll
                for (int t = 0; t < 8; ++t) {
                    const float p0 = exp2f(sacc[mt][t][0] - mn[2*mt]);
                    const float p1 = exp2f(sacc[mt][t][1] - mn[2*mt]);
                    const float p2 = exp2f(sacc[mt][t][2] - mn[2*mt+1]);
                    const float p3 = exp2f(sacc[mt][t][3] - mn[2*mt+1]);
                    sum[2*mt]   += p0 + p1;
                    sum[2*mt+1] += p2 + p3;
                    o[mt][t][0] *= al[2*mt];   o[mt][t][1] *= al[2*mt];
                    o[mt][t][2] *= al[2*mt+1]; o[mt][t][3] *= al[2*mt+1];
                    const int col = t * 8 + ql * 2;
                    float2 w0; w0.x = tf32r(p0); w0.y = tf32r(p1);
                    *(float2*)&Ps[r0 * FSK + col] = w0;
                    float2 w1; w1.x = tf32r(p2); w1.y = tf32r(p3);
                    *(float2*)&Ps[(r0 + 8) * FSK + col] = w1;
                }
            }
#pragma unroll
            for (int i = 0; i < 4; ++i) {
                sum[i] += __shfl_xor_sync(0xffffffffu, sum[i], 1);
                sum[i] += __shfl_xor_sync(0xffffffffu, sum[i], 2);
                l[i] = l[i] * al[i] + sum[i];
                m[i] = mn[i];
            }
            __syncwarp();   // P rows are warp-private

            // ---- O += P V ----
#pragma unroll
            for (int ks = 0; ks < 8; ++ks) {
                const int pc = ks * 8 + ql;
                uint32_t pa0[4], pa1[4];
                pa0[0] = __float_as_uint(Ps[rq * FSK + pc]);
                pa0[1] = __float_as_uint(Ps[(rq + 8) * FSK + pc]);
                pa0[2] = __float_as_uint(Ps[rq * FSK + pc + 4]);
                pa0[3] = __float_as_uint(Ps[(rq + 8) * FSK + pc + 4]);
                pa1[0] = __float_as_uint(Ps[(rq + 16) * FSK + pc]);
                pa1[1] = __float_as_uint(Ps[(rq + 24) * FSK + pc]);
                pa1[2] = __float_as_uint(Ps[(rq + 16) * FSK + pc + 4]);
                pa1[3] = __float_as_uint(Ps[(rq + 24) * FSK + pc + 4]);
#pragma unroll
                for (int t = 0; t < 8; ++t) {
                    const uint32_t b0 = tf32u(Vs[(ks * 8 + ql) * FSV + t * 8 + quad]);
                    const uint32_t b1 = tf32u(Vs[(ks * 8 + ql + 4) * FSV + t * 8 + quad]);
                    mma_tf32(o[0][t], pa0, b0, b1);
                    mma_tf32(o[1][t], pa1, b0, b1);
                }
            }
        }
        __syncthreads();   // all warps: buffer consumed, safe to overwrite next iter
    }

    // ---- epilogue: normalize and store 4 rows ----
    float inv[4];
#pragma unroll
    for (int i = 0; i < 4; ++i) inv[i] = 1.f / l[i];
#pragma unroll
    for (int mt = 0; mt < 2; ++mt)
#pragma unroll
        for (int t = 0; t < 8; ++t) {
            const int col = h * HD + t * 8 + ql * 2;
            float2 w;
            w.x = o[mt][t][0] * inv[2*mt]; w.y = o[mt][t][1] * inv[2*mt];
            *(float2*)(y + (rowBase + qrow[2*mt]) * CC + col) = w;
            w.x = o[mt][t][2] * inv[2*mt+1]; w.y = o[mt][t][3] * inv[2*mt+1];
            *(float2*)(y + (rowBase + qrow[2*mt+1]) * CC + col) = w;
        }
}

// ----------------------------------------------------------------------------
extern "C" void kernel_launch(void* const* d_in, const int* in_sizes, int n_in,
                              void* d_out, int out_size)
{
    const float *x = nullptr, *w_attn = nullptr, *b_attn = nullptr,
                *w_proj = nullptr, *b_proj = nullptr;
    for (int i = 0; i < n_in; ++i) {
        const int s = in_sizes[i];
        const float* p = (const float*)d_in[i];
        if      (s == MM * CC)   x      = p;
        else if (s == CC * NQKV) w_attn = p;
        else if (s == NQKV)      b_attn = p;
        else if (s == CC * CC)   w_proj = p;
        else if (s == CC)        b_proj = p;
    }
    float* out = (float*)d_out;

    float *qkv = nullptr, *y = nullptr;
    cudaGetSymbolAddress((void**)&qkv, g_qkv);
    cudaGetSymbolAddress((void**)&y, g_y);

    cudaFuncSetAttribute(flash_attn_tf32_kernel,
                         cudaFuncAttributeMaxDynamicSharedMemorySize,
                         (int)FA_SMEM_BYTES);

    dim3 blk(256);
    gemm_tf32_bias<<<dim3(NQKV / 128, MM / 128), blk>>>(
        x, w_attn, b_attn, qkv, MM, NQKV, CC);
    flash_attn_tf32_kernel<<<dim3(TT / 256, HH, BB), blk, FA_SMEM_BYTES>>>(qkv, y);
    gemm_tf32_bias<<<dim3(CC / 128, MM / 128), blk>>>(
        y, w_proj, b_proj, out, MM, CC, CC);
}

// round 12
// speedup vs baseline: 1.1195x; 1.1195x over previous
#include <cuda_runtime.h>
#include <math.h>
#include <stdint.h>

// Problem constants
#define BB   2
#define TT   4096
#define CC   768
#define HH   12
#define HD   64
#define MM   (BB*TT)        // 8192 rows
#define NQKV (3*CC)         // 2304

// Scratch (no cudaMalloc allowed)
__device__ float g_qkv[(size_t)MM * NQKV];
__device__ float g_y[(size_t)MM * CC];

// ----------------------------------------------------------------------------
// TF32 helpers
// ----------------------------------------------------------------------------
__device__ __forceinline__ float tf32r(float x) {
    uint32_t r;
    asm("cvt.rna.tf32.f32 %0, %1;" : "=r"(r) : "f"(x));
    return __uint_as_float(r);
}

__device__ __forceinline__ void mma_tf32(float* d, const uint32_t* a,
                                         uint32_t b0, uint32_t b1) {
    asm volatile(
        "mma.sync.aligned.m16n8k8.row.col.f32.tf32.tf32.f32 "
        "{%0,%1,%2,%3}, {%4,%5,%6,%7}, {%8,%9}, {%0,%1,%2,%3};\n"
        : "+f"(d[0]), "+f"(d[1]), "+f"(d[2]), "+f"(d[3])
        : "r"(a[0]), "r"(a[1]), "r"(a[2]), "r"(a[3]), "r"(b0), "r"(b1));
}

// ----------------------------------------------------------------------------
// TF32 tensor-core GEMM (measured-stable: 248us QKV). Stride 136, conflict-free
// fragment loads. Block 128x128, BK=16, 8 warps (2m x 4n). UNCHANGED.
// ----------------------------------------------------------------------------
__global__ __launch_bounds__(256)
void gemm_tf32_bias(const float* __restrict__ A, const float* __restrict__ Bm,
                    const float* __restrict__ bias, float* __restrict__ Cm,
                    int M, int N, int K)
{
    __shared__ float As[16][136];
    __shared__ float Bs[16][136];

    const int tid  = threadIdx.x;
    const int lane = tid & 31, warp = tid >> 5;
    const int quad = lane >> 2, ql = lane & 3;
    const int wm = (warp & 1) * 64;
    const int wn = (warp >> 1) * 32;
    const int cm = blockIdx.y * 128, cn = blockIdx.x * 128;

    const int arow = tid >> 2, acol = (tid & 3) << 2;
    const int brow = tid >> 5, bcol = (tid & 31) << 2;

    const float* Ab = A + (size_t)cm * K;
    const float* Bb = Bm + cn;

    float acc[4][4][4];
#pragma unroll
    for (int mt = 0; mt < 4; ++mt)
#pragma unroll
        for (int nt = 0; nt < 4; ++nt)
#pragma unroll
            for (int f = 0; f < 4; ++f) acc[mt][nt][f] = 0.f;

    float4 pa0 = *(const float4*)(Ab + (size_t)arow * K + acol);
    float4 pa1 = *(const float4*)(Ab + (size_t)(arow + 64) * K + acol);
    float4 pb0 = *(const float4*)(Bb + (size_t)brow * N + bcol);
    float4 pb1 = *(const float4*)(Bb + (size_t)(brow + 8) * N + bcol);

    const int NK = K >> 4;
    for (int kt = 0; kt < NK; ++kt) {
        As[acol + 0][arow]      = tf32r(pa0.x);
        As[acol + 1][arow]      = tf32r(pa0.y);
        As[acol + 2][arow]      = tf32r(pa0.z);
        As[acol + 3][arow]      = tf32r(pa0.w);
        As[acol + 0][arow + 64] = tf32r(pa1.x);
        As[acol + 1][arow + 64] = tf32r(pa1.y);
        As[acol + 2][arow + 64] = tf32r(pa1.z);
        As[acol + 3][arow + 64] = tf32r(pa1.w);
        float4 tb;
        tb.x = tf32r(pb0.x); tb.y = tf32r(pb0.y);
        tb.z = tf32r(pb0.z); tb.w = tf32r(pb0.w);
        *(float4*)&Bs[brow][bcol] = tb;
        tb.x = tf32r(pb1.x); tb.y = tf32r(pb1.y);
        tb.z = tf32r(pb1.z); tb.w = tf32r(pb1.w);
        *(float4*)&Bs[brow + 8][bcol] = tb;
        __syncthreads();

        if (kt + 1 < NK) {
            const int k0 = (kt + 1) << 4;
            pa0 = *(const float4*)(Ab + (size_t)arow * K + k0 + acol);
            pa1 = *(const float4*)(Ab + (size_t)(arow + 64) * K + k0 + acol);
            pb0 = *(const float4*)(Bb + (size_t)(k0 + brow) * N + bcol);
            pb1 = *(const float4*)(Bb + (size_t)(k0 + brow + 8) * N + bcol);
        }

#pragma unroll
        for (int ks = 0; ks < 2; ++ks) {
            const int kk = ks * 8;
            uint32_t af[4][4];
#pragma unroll
            for (int mt = 0; mt < 4; ++mt) {
                const int mb = wm + mt * 16;
                af[mt][0] = __float_as_uint(As[kk + ql][mb + quad]);
                af[mt][1] = __float_as_uint(As[kk + ql][mb + quad + 8]);
                af[mt][2] = __float_as_uint(As[kk + ql + 4][mb + quad]);
                af[mt][3] = __float_as_uint(As[kk + ql + 4][mb + quad + 8]);
            }
#pragma unroll
            for (int nt = 0; nt < 4; ++nt) {
                const uint32_t b0 = __float_as_uint(Bs[kk + ql][wn + nt * 8 + quad]);
                const uint32_t b1 = __float_as_uint(Bs[kk + ql + 4][wn + nt * 8 + quad]);
#pragma unroll
                for (int mt = 0; mt < 4; ++mt)
                    mma_tf32(acc[mt][nt], af[mt], b0, b1);
            }
        }
        __syncthreads();
    }

#pragma unroll
    for (int mt = 0; mt < 4; ++mt) {
        const int r0 = cm + wm + mt * 16 + quad;
#pragma unroll
        for (int nt = 0; nt < 4; ++nt) {
            const int c = cn + wn + nt * 8 + ql * 2;
            const float bx = bias[c], by = bias[c + 1];
            float2 w;
            w.x = acc[mt][nt][0] + bx; w.y = acc[mt][nt][1] + by;
            *(float2*)(Cm + (size_t)r0 * N + c) = w;
            w.x = acc[mt][nt][2] + bx; w.y = acc[mt][nt][3] + by;
            *(float2*)(Cm + (size_t)(r0 + 8) * N + c) = w;
        }
    }
}

// ----------------------------------------------------------------------------
// Flash attention v4: R9 inner loop (store-time tf32 conversion), but
// CTA = 128 q-rows / 128 threads / 4 warps  ->  2 CTAs per SM.
// Cross-CTA overlap hides the synchronous K/V load + barrier phases that
// were exposed at 1 CTA/SM. Warp m-tile stays 32 rows.
// smem/CTA = (128+128)*68*4 + 64*68*4 + 64*72*4 = 105472 B  (2 fit in 228KB).
// Long-running (late-causal) CTAs launch first: qb = gridDim.x-1-blockIdx.x.
// ----------------------------------------------------------------------------
#define FSK 68
#define FSV 72
#define FA_SMEM_BYTES ((256 * FSK + 64 * FSK + 64 * FSV) * sizeof(float))

__global__ __launch_bounds__(128, 2)
void flash_attn_tf32_kernel(const float* __restrict__ qkv, float* __restrict__ y)
{
    extern __shared__ float sm[];
    float* Qs = sm;                       // [128][68]
    float* Ps = Qs + 128 * FSK;           // [128][68]
    float* Ks = Ps + 128 * FSK;           // [64][68]
    float* Vs = Ks + 64 * FSK;            // [64][72]

    const int tid  = threadIdx.x;
    const int warp = tid >> 5;            // 0..3
    const int lane = tid & 31;
    const int quad = lane >> 2;
    const int ql   = lane & 3;
    const int h  = blockIdx.y;
    const int b  = blockIdx.z;
    const int qb = gridDim.x - 1 - blockIdx.x;   // big blocks first
    const int q0 = qb * 128;
    const size_t rowBase = (size_t)b * TT;
    const int qOff = h * HD, kOff = CC + h * HD, vOff = 2 * CC + h * HD;

    const int rq = warp * 32 + quad;      // local base row

    // ---- load Q tile (128 x 64), tf32-converted ----
#pragma unroll
    for (int p = 0; p < 16; ++p) {
        const int f4 = tid + 128 * p;               // 0..2047
        const int r = f4 >> 4, c = (f4 & 15) << 2;
        const float4 v = *(const float4*)(qkv + (rowBase + q0 + r) * NQKV + qOff + c);
        Qs[r * FSK + c + 0] = tf32r(v.x);
        Qs[r * FSK + c + 1] = tf32r(v.y);
        Qs[r * FSK + c + 2] = tf32r(v.z);
        Qs[r * FSK + c + 3] = tf32r(v.w);
    }
    __syncthreads();

    // ---- mt0 Q fragments in registers (rows rq, rq+8) ----
    uint32_t qa0[8][4];
#pragma unroll
    for (int ks = 0; ks < 8; ++ks) {
        const int c = ks * 8 + ql;
        qa0[ks][0] = __float_as_uint(Qs[rq * FSK + c]);
        qa0[ks][1] = __float_as_uint(Qs[(rq + 8) * FSK + c]);
        qa0[ks][2] = __float_as_uint(Qs[rq * FSK + c + 4]);
        qa0[ks][3] = __float_as_uint(Qs[(rq + 8) * FSK + c + 4]);
    }

    float m[4], l[4];
#pragma unroll
    for (int i = 0; i < 4; ++i) { m[i] = -INFINITY; l[i] = 0.f; }
    int qrow[4];
    qrow[0] = q0 + rq;       qrow[1] = q0 + rq + 8;
    qrow[2] = q0 + rq + 16;  qrow[3] = q0 + rq + 24;
    const int wmax = q0 + warp * 32 + 31;

    float o[2][8][4];
#pragma unroll
    for (int mt = 0; mt < 2; ++mt)
#pragma unroll
        for (int t = 0; t < 8; ++t)
            o[mt][t][0] = o[mt][t][1] = o[mt][t][2] = o[mt][t][3] = 0.f;

    const float C2 = 0.18033688011112042f;   // log2(e) / sqrt(64)

    const int nkt = (q0 >> 6) + 2;
    for (int kt = 0; kt < nkt; ++kt) {
        const int k0 = kt << 6;
        __syncthreads();   // prior iter's Ks/Vs reads done
        // ---- load K (stride 68) and V (stride 72), tf32-converted ----
#pragma unroll
        for (int p = 0; p < 8; ++p) {
            const int f4 = tid + 128 * p;            // 0..1023
            const int r = f4 >> 4, c = (f4 & 15) << 2;
            const size_t g = (rowBase + k0 + r) * NQKV;
            const float4 kv = *(const float4*)(qkv + g + kOff + c);
            Ks[r * FSK + c + 0] = tf32r(kv.x);
            Ks[r * FSK + c + 1] = tf32r(kv.y);
            Ks[r * FSK + c + 2] = tf32r(kv.z);
            Ks[r * FSK + c + 3] = tf32r(kv.w);
            const float4 vv = *(const float4*)(qkv + g + vOff + c);
            Vs[r * FSV + c + 0] = tf32r(vv.x);
            Vs[r * FSV + c + 1] = tf32r(vv.y);
            Vs[r * FSV + c + 2] = tf32r(vv.z);
            Vs[r * FSV + c + 3] = tf32r(vv.w);
        }
        __syncthreads();

        if (k0 > wmax) continue;   // fully-masked tile for this warp

        // ---- S = Q K^T (2 m-frags x 8 n-tiles x 8 k-steps) ----
        float sacc[2][8][4];
#pragma unroll
        for (int mt = 0; mt < 2; ++mt)
#pragma unroll
            for (int t = 0; t < 8; ++t)
                sacc[mt][t][0] = sacc[mt][t][1] = sacc[mt][t][2] = sacc[mt][t][3] = 0.f;
#pragma unroll
        for (int ks = 0; ks < 8; ++ks) {
            const int c = ks * 8 + ql;
            uint32_t qa1[4];
            qa1[0] = __float_as_uint(Qs[(rq + 16) * FSK + c]);
            qa1[1] = __float_as_uint(Qs[(rq + 24) * FSK + c]);
            qa1[2] = __float_as_uint(Qs[(rq + 16) * FSK + c + 4]);
            qa1[3] = __float_as_uint(Qs[(rq + 24) * FSK + c + 4]);
#pragma unroll
            for (int t = 0; t < 8; ++t) {
                const uint32_t b0 = __float_as_uint(Ks[(t * 8 + quad) * FSK + c]);
                const uint32_t b1 = __float_as_uint(Ks[(t * 8 + quad) * FSK + c + 4]);
                mma_tf32(sacc[0][t], qa0[ks], b0, b1);
                mma_tf32(sacc[1][t], qa1, b0, b1);
            }
        }

        // ---- scale + causal mask + row max ----
        float rm[4];
        rm[0] = rm[1] = rm[2] = rm[3] = -INFINITY;
#pragma unroll
        for (int mt = 0; mt < 2; ++mt)
#pragma unroll
            for (int t = 0; t < 8; ++t) {
                const int gc = k0 + t * 8 + ql * 2;
                float v0 = sacc[mt][t][0] * C2; if (gc     > qrow[2*mt])   v0 = -INFINITY;
                float v1 = sacc[mt][t][1] * C2; if (gc + 1 > qrow[2*mt])   v1 = -INFINITY;
                float v2 = sacc[mt][t][2] * C2; if (gc     > qrow[2*mt+1]) v2 = -INFINITY;
                float v3 = sacc[mt][t][3] * C2; if (gc + 1 > qrow[2*mt+1]) v3 = -INFINITY;
                sacc[mt][t][0] = v0; sacc[mt][t][1] = v1;
                sacc[mt][t][2] = v2; sacc[mt][t][3] = v3;
                rm[2*mt]   = fmaxf(rm[2*mt],   fmaxf(v0, v1));
                rm[2*mt+1] = fmaxf(rm[2*mt+1], fmaxf(v2, v3));
            }
        float mn[4], al[4];
#pragma unroll
        for (int i = 0; i < 4; ++i) {
            rm[i] = fmaxf(rm[i], __shfl_xor_sync(0xffffffffu, rm[i], 1));
            rm[i] = fmaxf(rm[i], __shfl_xor_sync(0xffffffffu, rm[i], 2));
            mn[i] = fmaxf(m[i], rm[i]);
            al[i] = exp2f(m[i] - mn[i]);
        }

        // ---- exp, P write, O rescale ----
        float sum[4];
        sum[0] = sum[1] = sum[2] = sum[3] = 0.f;
#pragma unroll
        for (int mt = 0; mt < 2; ++mt) {
            const int r0 = rq + mt * 16;
#pragma unroll
            for (int t = 0; t < 8; ++t) {
                const float p0 = exp2f(sacc[mt][t][0] - mn[2*mt]);
                const float p1 = exp2f(sacc[mt][t][1] - mn[2*mt]);
                const float p2 = exp2f(sacc[mt][t][2] - mn[2*mt+1]);
                const float p3 = exp2f(sacc[mt][t][3] - mn[2*mt+1]);
                sum[2*mt]   += p0 + p1;
                sum[2*mt+1] += p2 + p3;
                o[mt][t][0] *= al[2*mt];   o[mt][t][1] *= al[2*mt];
                o[mt][t][2] *= al[2*mt+1]; o[mt][t][3] *= al[2*mt+1];
                const int col = t * 8 + ql * 2;
                float2 w0; w0.x = tf32r(p0); w0.y = tf32r(p1);
                *(float2*)&Ps[r0 * FSK + col] = w0;
                float2 w1; w1.x = tf32r(p2); w1.y = tf32r(p3);
                *(float2*)&Ps[(r0 + 8) * FSK + col] = w1;
            }
        }
#pragma unroll
        for (int i = 0; i < 4; ++i) {
            sum[i] += __shfl_xor_sync(0xffffffffu, sum[i], 1);
            sum[i] += __shfl_xor_sync(0xffffffffu, sum[i], 2);
            l[i] = l[i] * al[i] + sum[i];
            m[i] = mn[i];
        }
        __syncwarp();   // P rows are warp-private

        // ---- O += P V ----
#pragma unroll
        for (int ks = 0; ks < 8; ++ks) {
            const int pc = ks * 8 + ql;
            uint32_t pa0[4], pa1[4];
            pa0[0] = __float_as_uint(Ps[rq * FSK + pc]);
            pa0[1] = __float_as_uint(Ps[(rq + 8) * FSK + pc]);
            pa0[2] = __float_as_uint(Ps[rq * FSK + pc + 4]);
            pa0[3] = __float_as_uint(Ps[(rq + 8) * FSK + pc + 4]);
            pa1[0] = __float_as_uint(Ps[(rq + 16) * FSK + pc]);
            pa1[1] = __float_as_uint(Ps[(rq + 24) * FSK + pc]);
            pa1[2] = __float_as_uint(Ps[(rq + 16) * FSK + pc + 4]);
            pa1[3] = __float_as_uint(Ps[(rq + 24) * FSK + pc + 4]);
#pragma unroll
            for (int t = 0; t < 8; ++t) {
                const uint32_t b0 = __float_as_uint(Vs[(ks * 8 + ql) * FSV + t * 8 + quad]);
                const uint32_t b1 = __float_as_uint(Vs[(ks * 8 + ql + 4) * FSV + t * 8 + quad]);
                mma_tf32(o[0][t], pa0, b0, b1);
                mma_tf32(o[1][t], pa1, b0, b1);
            }
        }
        __syncwarp();
    }

    // ---- epilogue: normalize and store 4 rows ----
    float inv[4];
#pragma unroll
    for (int i = 0; i < 4; ++i) inv[i] = 1.f / l[i];
#pragma unroll
    for (int mt = 0; mt < 2; ++mt)
#pragma unroll
        for (int t = 0; t < 8; ++t) {
            const int col = h * HD + t * 8 + ql * 2;
            float2 w;
            w.x = o[mt][t][0] * inv[2*mt]; w.y = o[mt][t][1] * inv[2*mt];
            *(float2*)(y + (rowBase + qrow[2*mt]) * CC + col) = w;
            w.x = o[mt][t][2] * inv[2*mt+1]; w.y = o[mt][t][3] * inv[2*mt+1];
            *(float2*)(y + (rowBase + qrow[2*mt+1]) * CC + col) = w;
        }
}

// ----------------------------------------------------------------------------
extern "C" void kernel_launch(void* const* d_in, const int* in_sizes, int n_in,
                              void* d_out, int out_size)
{
    const float *x = nullptr, *w_attn = nullptr, *b_attn = nullptr,
                *w_proj = nullptr, *b_proj = nullptr;
    for (int i = 0; i < n_in; ++i) {
        const int s = in_sizes[i];
        const float* p = (const float*)d_in[i];
        if      (s == MM * CC)   x      = p;
        else if (s == CC * NQKV) w_attn = p;
        else if (s == NQKV)      b_attn = p;
        else if (s == CC * CC)   w_proj = p;
        else if (s == CC)        b_proj = p;
    }
    float* out = (float*)d_out;

    float *qkv = nullptr, *y = nullptr;
    cudaGetSymbolAddress((void**)&qkv, g_qkv);
    cudaGetSymbolAddress((void**)&y, g_y);

    cudaFuncSetAttribute(flash_attn_tf32_kernel,
                         cudaFuncAttributeMaxDynamicSharedMemorySize,
                         (int)FA_SMEM_BYTES);

    gemm_tf32_bias<<<dim3(NQKV / 128, MM / 128), dim3(256)>>>(
        x, w_attn, b_attn, qkv, MM, NQKV, CC);
    flash_attn_tf32_kernel<<<dim3(TT / 128, HH, BB), dim3(128), FA_SMEM_BYTES>>>(qkv, y);
    gemm_tf32_bias<<<dim3(CC / 128, MM / 128), dim3(256)>>>(
        y, w_proj, b_proj, out, MM, CC, CC);
}